// round 1
// baseline (speedup 1.0000x reference)
#include <cuda_runtime.h>
#include <cuda_fp16.h>
#include <cuda_bf16.h>
#include <cstdint>

// Problem constants
#define BHD 32       // B*H
#define SEQ 2048     // N
#define HD  64       // D
#define BM  64       // rows per CTA tile
#define KT  64       // key tokens per k-tile
#define QS  72       // bf16 smem row stride (conflict-free mma frag loads)
#define VS  70       // fp16 smem row stride for transposed V (conflict-free stores)

#define OUT_ELEMS ((size_t)BHD * SEQ * HD)   // offset of score region in d_out

// scratch: per-(b,h) column sums of v (no device allocation allowed -> __device__ global)
__device__ float g_vsum[BHD * HD];

__global__ void hd_vsum_kernel(const float* __restrict__ v) {
    int bh = blockIdx.x;
    int d = threadIdx.x;                   // 64 threads
    const float* vp = v + (size_t)bh * SEQ * HD + d;
    float s = 0.f;
    #pragma unroll 8
    for (int t = 0; t < SEQ; ++t) s += vp[(size_t)t * HD];
    g_vsum[bh * HD + d] = s;
}

__device__ __forceinline__ void mma_bf16(float* c, uint32_t a0, uint32_t a1, uint32_t a2, uint32_t a3,
                                         uint32_t b0, uint32_t b1) {
    asm volatile(
        "mma.sync.aligned.m16n8k16.row.col.f32.bf16.bf16.f32 "
        "{%0,%1,%2,%3},{%4,%5,%6,%7},{%8,%9},{%0,%1,%2,%3};\n"
        : "+f"(c[0]), "+f"(c[1]), "+f"(c[2]), "+f"(c[3])
        : "r"(a0), "r"(a1), "r"(a2), "r"(a3), "r"(b0), "r"(b1));
}

__device__ __forceinline__ void mma_f16(float* c, uint32_t a0, uint32_t a1, uint32_t a2, uint32_t a3,
                                        uint32_t b0, uint32_t b1) {
    asm volatile(
        "mma.sync.aligned.m16n8k16.row.col.f32.f16.f16.f32 "
        "{%0,%1,%2,%3},{%4,%5,%6,%7},{%8,%9},{%0,%1,%2,%3};\n"
        : "+f"(c[0]), "+f"(c[1]), "+f"(c[2]), "+f"(c[3])
        : "r"(a0), "r"(a1), "r"(a2), "r"(a3), "r"(b0), "r"(b1));
}

// load a 64x64 fp32 tile, apply 2x-1, store bf16 to smem (row stride QS)
__device__ __forceinline__ void load_tile_2xm1_bf16(const float* __restrict__ gsrc,
                                                    __nv_bfloat16* __restrict__ dst, int tid) {
    const float4* g4 = (const float4*)gsrc;
    #pragma unroll
    for (int i = 0; i < 8; ++i) {
        int f = i * 128 + tid;
        int r = f >> 4;
        int c4 = (f & 15) << 2;
        float4 x = g4[f];
        __nv_bfloat162 ab, cd;
        ab.x = __float2bfloat16(2.f * x.x - 1.f);
        ab.y = __float2bfloat16(2.f * x.y - 1.f);
        cd.x = __float2bfloat16(2.f * x.z - 1.f);
        cd.y = __float2bfloat16(2.f * x.w - 1.f);
        *(__nv_bfloat162*)&dst[r * QS + c4]     = ab;
        *(__nv_bfloat162*)&dst[r * QS + c4 + 2] = cd;
    }
}

// QK^T MMA: S[16x64] per warp from q a-frags and bf16 K tile in smem
__device__ __forceinline__ void qk_mma(const __nv_bfloat16* __restrict__ sk,
                                       const uint32_t aq[4][4], int g, int qd, float S[8][4]) {
    #pragma unroll
    for (int nb = 0; nb < 8; ++nb) {
        S[nb][0] = 0.f; S[nb][1] = 0.f; S[nb][2] = 0.f; S[nb][3] = 0.f;
    }
    #pragma unroll
    for (int j = 0; j < 4; ++j) {
        int bk = j * 16 + qd * 2;
        #pragma unroll
        for (int nb = 0; nb < 8; ++nb) {
            int n = nb * 8 + g;
            uint32_t b0 = *(const uint32_t*)&sk[n * QS + bk];
            uint32_t b1 = *(const uint32_t*)&sk[n * QS + bk + 8];
            mma_bf16(S[nb], aq[j][0], aq[j][1], aq[j][2], aq[j][3], b0, b1);
        }
    }
}

__device__ __forceinline__ uint32_t pack_h2(float a, float b) {
    __half2 h = __floats2half2_rn(a, b);
    return *(uint32_t*)&h;
}

__global__ __launch_bounds__(128)
void hd_attn_kernel(const float* __restrict__ q, const float* __restrict__ k,
                    const float* __restrict__ v, float* __restrict__ outp) {
    __shared__ __nv_bfloat16 sq[BM * QS];
    __shared__ __nv_bfloat16 sk[KT * QS];
    __shared__ half svh[HD * VS];     // v^T hi fp16: [d][token]
    __shared__ half svl[HD * VS];     // v^T lo fp16
    __shared__ float srs[BM];         // row sums
    __shared__ float svs[HD];         // vsum for this bh

    const int tid = threadIdx.x;
    const int w = tid >> 5;
    const int lane = tid & 31;
    const int g = lane >> 2;          // 0..7
    const int qd = lane & 3;          // 0..3
    const int bh = blockIdx.y;
    const int m0 = blockIdx.x * BM;
    const size_t base = (size_t)bh * SEQ * HD;
    const float LSCALE = 0.0078125f;  // 1/128

    // Q tile (rows m0..m0+63 contiguous in gmem)
    load_tile_2xm1_bf16(q + base + (size_t)m0 * HD, sq, tid);
    if (tid < HD) svs[tid] = g_vsum[bh * HD + tid];
    __syncthreads();

    // per-warp Q A-fragments (rows r1, r1+8; 4 k-steps over D=64)
    const int r1 = w * 16 + g;
    uint32_t aq[4][4];
    #pragma unroll
    for (int j = 0; j < 4; ++j) {
        int k0 = j * 16 + qd * 2;
        aq[j][0] = *(const uint32_t*)&sq[r1 * QS + k0];
        aq[j][1] = *(const uint32_t*)&sq[(r1 + 8) * QS + k0];
        aq[j][2] = *(const uint32_t*)&sq[r1 * QS + k0 + 8];
        aq[j][3] = *(const uint32_t*)&sq[(r1 + 8) * QS + k0 + 8];
    }

    // ---------------- pass 1: row sums of exp(sim/128) ----------------
    float rs0 = 0.f, rs1 = 0.f;
    for (int kb = 0; kb < SEQ / KT; ++kb) {
        __syncthreads();
        load_tile_2xm1_bf16(k + base + (size_t)kb * KT * HD, sk, tid);
        __syncthreads();

        float S[8][4];
        qk_mma(sk, aq, g, qd, S);
        #pragma unroll
        for (int nb = 0; nb < 8; ++nb) {
            rs0 += __expf(S[nb][0] * LSCALE) + __expf(S[nb][1] * LSCALE);
            rs1 += __expf(S[nb][2] * LSCALE) + __expf(S[nb][3] * LSCALE);
        }
    }
    rs0 += __shfl_xor_sync(0xffffffffu, rs0, 1);
    rs0 += __shfl_xor_sync(0xffffffffu, rs0, 2);
    rs1 += __shfl_xor_sync(0xffffffffu, rs1, 1);
    rs1 += __shfl_xor_sync(0xffffffffu, rs1, 2);
    if (qd == 0) { srs[r1] = rs0; srs[r1 + 8] = rs1; }
    __syncthreads();
    const float inv0 = 1.f / srs[r1];
    const float inv1 = 1.f / srs[r1 + 8];

    // ---------------- pass 2: write score, accumulate (p-1)·V ----------------
    float O[8][4];
    #pragma unroll
    for (int nb = 0; nb < 8; ++nb) { O[nb][0]=0.f; O[nb][1]=0.f; O[nb][2]=0.f; O[nb][3]=0.f; }

    float* scr = outp + OUT_ELEMS + (size_t)bh * SEQ * SEQ;

    for (int kb = 0; kb < SEQ / KT; ++kb) {
        __syncthreads();
        load_tile_2xm1_bf16(k + base + (size_t)kb * KT * HD, sk, tid);
        // V tile -> transposed fp16 hi/lo in smem
        {
            const float* vg = v + base + (size_t)kb * KT * HD;
            #pragma unroll
            for (int i = 0; i < 32; ++i) {
                int f = i * 128 + tid;
                int r = f >> 6;      // token within tile
                int c = f & 63;      // d
                float x = vg[f];
                half h = __float2half_rn(x);
                half l = __float2half_rn(x - __half2float(h));
                svh[c * VS + r] = h;
                svl[c * VS + r] = l;
            }
        }
        __syncthreads();

        float S[8][4];
        qk_mma(sk, aq, g, qd, S);

        // exp, normalized score store, e = p-1 kept in S regs (A-frag layout reuse)
        #pragma unroll
        for (int nb = 0; nb < 8; ++nb) {
            float p0 = __expf(S[nb][0] * LSCALE);
            float p1 = __expf(S[nb][1] * LSCALE);
            float p2 = __expf(S[nb][2] * LSCALE);
            float p3 = __expf(S[nb][3] * LSCALE);
            int col = kb * KT + nb * 8 + qd * 2;
            float2 s0 = make_float2(p0 * inv0, p1 * inv0);
            float2 s1 = make_float2(p2 * inv1, p3 * inv1);
            *(float2*)&scr[(size_t)(m0 + r1) * SEQ + col]     = s0;
            *(float2*)&scr[(size_t)(m0 + r1 + 8) * SEQ + col] = s1;
            S[nb][0] = p0 - 1.f; S[nb][1] = p1 - 1.f;
            S[nb][2] = p2 - 1.f; S[nb][3] = p3 - 1.f;
        }

        // O += e · v_hi + e · v_lo   (fp16 MMA, fp32 accum)
        #pragma unroll
        for (int j = 0; j < 4; ++j) {
            uint32_t ea0 = pack_h2(S[2*j][0],   S[2*j][1]);
            uint32_t ea1 = pack_h2(S[2*j][2],   S[2*j][3]);
            uint32_t ea2 = pack_h2(S[2*j+1][0], S[2*j+1][1]);
            uint32_t ea3 = pack_h2(S[2*j+1][2], S[2*j+1][3]);
            int bk = j * 16 + qd * 2;
            #pragma unroll
            for (int nb = 0; nb < 8; ++nb) {
                int n = nb * 8 + g;
                uint32_t b0 = *(const uint32_t*)&svh[n * VS + bk];
                uint32_t b1 = *(const uint32_t*)&svh[n * VS + bk + 8];
                mma_f16(O[nb], ea0, ea1, ea2, ea3, b0, b1);
                uint32_t c0 = *(const uint32_t*)&svl[n * VS + bk];
                uint32_t c1 = *(const uint32_t*)&svl[n * VS + bk + 8];
                mma_f16(O[nb], ea0, ea1, ea2, ea3, c0, c1);
            }
        }
    }

    // out = (vsum + O) / rowsum
    #pragma unroll
    for (int nb = 0; nb < 8; ++nb) {
        int d0 = nb * 8 + qd * 2;
        float vs0 = svs[d0], vs1 = svs[d0 + 1];
        float2 o0 = make_float2((O[nb][0] + vs0) * inv0, (O[nb][1] + vs1) * inv0);
        float2 o1 = make_float2((O[nb][2] + vs0) * inv1, (O[nb][3] + vs1) * inv1);
        *(float2*)&outp[base + (size_t)(m0 + r1) * HD + d0]     = o0;
        *(float2*)&outp[base + (size_t)(m0 + r1 + 8) * HD + d0] = o1;
    }
}

extern "C" void kernel_launch(void* const* d_in, const int* in_sizes, int n_in,
                              void* d_out, int out_size) {
    const float* q = (const float*)d_in[0];
    const float* k = (const float*)d_in[1];
    const float* v = (const float*)d_in[2];
    float* o = (float*)d_out;

    hd_vsum_kernel<<<BHD, HD>>>(v);
    dim3 grid(SEQ / BM, BHD);
    hd_attn_kernel<<<grid, 128>>>(q, k, v, o);
}

// round 2
// speedup vs baseline: 2.1889x; 2.1889x over previous
#include <cuda_runtime.h>
#include <cuda_fp16.h>
#include <cuda_bf16.h>
#include <cstdint>

#define BHD 32       // B*H
#define SEQ 2048     // N
#define HD  64       // D
#define BM  128      // q rows per CTA
#define KT  64       // key tokens per tile
#define ST  72       // smem row stride in halves (36 words -> ldmatrix conflict-free)

#define OUT_ELEMS ((size_t)BHD * SEQ * HD)

__device__ float g_vsum[BHD * HD];

// ---------------- vsum: per-(b,h) column sums of v ----------------
__global__ __launch_bounds__(1024)
void hd_vsum_kernel(const float* __restrict__ v) {
    __shared__ float red[16][64];
    int bh = blockIdx.x;
    int d = threadIdx.x & 63;
    int s = threadIdx.x >> 6;    // 0..15
    const float* vp = v + (size_t)bh * SEQ * HD + (size_t)s * 128 * HD + d;
    float acc = 0.f;
    #pragma unroll 8
    for (int t = 0; t < 128; ++t) acc += vp[t * HD];
    red[s][d] = acc;
    __syncthreads();
    if (threadIdx.x < 64) {
        float r = 0.f;
        #pragma unroll
        for (int i = 0; i < 16; ++i) r += red[i][threadIdx.x];
        g_vsum[bh * HD + threadIdx.x] = r;
    }
}

// ---------------- mma / ldmatrix helpers ----------------
__device__ __forceinline__ void mma_bf16(float* c, const uint32_t a[4], uint32_t b0, uint32_t b1) {
    asm volatile(
        "mma.sync.aligned.m16n8k16.row.col.f32.bf16.bf16.f32 "
        "{%0,%1,%2,%3},{%4,%5,%6,%7},{%8,%9},{%0,%1,%2,%3};\n"
        : "+f"(c[0]), "+f"(c[1]), "+f"(c[2]), "+f"(c[3])
        : "r"(a[0]), "r"(a[1]), "r"(a[2]), "r"(a[3]), "r"(b0), "r"(b1));
}
__device__ __forceinline__ void mma_f16(float* c, const uint32_t a[4], uint32_t b0, uint32_t b1) {
    asm volatile(
        "mma.sync.aligned.m16n8k16.row.col.f32.f16.f16.f32 "
        "{%0,%1,%2,%3},{%4,%5,%6,%7},{%8,%9},{%0,%1,%2,%3};\n"
        : "+f"(c[0]), "+f"(c[1]), "+f"(c[2]), "+f"(c[3])
        : "r"(a[0]), "r"(a[1]), "r"(a[2]), "r"(a[3]), "r"(b0), "r"(b1));
}
__device__ __forceinline__ void ldsm_x4(uint32_t& r0, uint32_t& r1, uint32_t& r2, uint32_t& r3, uint32_t a) {
    asm volatile("ldmatrix.sync.aligned.m8n8.x4.shared.b16 {%0,%1,%2,%3}, [%4];\n"
        : "=r"(r0), "=r"(r1), "=r"(r2), "=r"(r3) : "r"(a));
}
__device__ __forceinline__ void ldsm_x4_t(uint32_t& r0, uint32_t& r1, uint32_t& r2, uint32_t& r3, uint32_t a) {
    asm volatile("ldmatrix.sync.aligned.m8n8.x4.trans.shared.b16 {%0,%1,%2,%3}, [%4];\n"
        : "=r"(r0), "=r"(r1), "=r"(r2), "=r"(r3) : "r"(a));
}
__device__ __forceinline__ uint32_t smem_u32(const void* p) {
    return (uint32_t)__cvta_generic_to_shared(p);
}
__device__ __forceinline__ uint32_t pack_h2(float a, float b) {
    __half2 h = __floats2half2_rn(a, b);
    return *(uint32_t*)&h;
}

// load ROWSx64 fp32 tile, apply 2x-1, store bf16 (stride ST), 256 threads
template<int ROWS>
__device__ __forceinline__ void load_2xm1(const float* __restrict__ gsrc,
                                          __nv_bfloat16* __restrict__ dst, int tid) {
    const float4* g4 = (const float4*)gsrc;
    #pragma unroll
    for (int i = 0; i < ROWS / 16; ++i) {
        int f = i * 256 + tid;
        int r = f >> 4;
        int c = (f & 15) << 2;
        float4 x = g4[f];
        __nv_bfloat162 ab, cd;
        ab.x = __float2bfloat16(2.f * x.x - 1.f);
        ab.y = __float2bfloat16(2.f * x.y - 1.f);
        cd.x = __float2bfloat16(2.f * x.z - 1.f);
        cd.y = __float2bfloat16(2.f * x.w - 1.f);
        *(__nv_bfloat162*)&dst[r * ST + c]     = ab;
        *(__nv_bfloat162*)&dst[r * ST + c + 2] = cd;
    }
}

// load 64x64 fp32 V tile -> fp16 hi/lo (stride ST), [token][d], 256 threads
__device__ __forceinline__ void load_v(const float* __restrict__ gsrc,
                                       half* __restrict__ dh, half* __restrict__ dl, int tid) {
    const float4* g4 = (const float4*)gsrc;
    #pragma unroll
    for (int i = 0; i < 4; ++i) {
        int f = i * 256 + tid;
        int r = f >> 4;
        int c = (f & 15) << 2;
        float4 x = g4[f];
        half h0 = __float2half_rn(x.x), h1 = __float2half_rn(x.y);
        half h2 = __float2half_rn(x.z), h3 = __float2half_rn(x.w);
        half l0 = __float2half_rn(x.x - __half2float(h0));
        half l1 = __float2half_rn(x.y - __half2float(h1));
        half l2 = __float2half_rn(x.z - __half2float(h2));
        half l3 = __float2half_rn(x.w - __half2float(h3));
        *(half2*)&dh[r * ST + c]     = __halves2half2(h0, h1);
        *(half2*)&dh[r * ST + c + 2] = __halves2half2(h2, h3);
        *(half2*)&dl[r * ST + c]     = __halves2half2(l0, l1);
        *(half2*)&dl[r * ST + c + 2] = __halves2half2(l2, l3);
    }
}

__global__ __launch_bounds__(256, 2)
void hd_attn_kernel(const float* __restrict__ q, const float* __restrict__ k,
                    const float* __restrict__ v, float* __restrict__ outp) {
    __shared__ __nv_bfloat16 sq[BM * ST];
    __shared__ __nv_bfloat16 sk[KT * ST];
    __shared__ half svh[KT * ST];
    __shared__ half svl[KT * ST];
    __shared__ float srs[BM];
    __shared__ float svs[HD];

    const int tid = threadIdx.x;
    const int w = tid >> 5;
    const int lane = tid & 31;
    const int g = lane >> 2;          // 0..7
    const int qd = lane & 3;          // 0..3
    const int group = lane >> 3;      // 0..3 (ldmatrix address group)
    const int lr = lane & 7;
    const int bh = blockIdx.y;
    const int m0 = blockIdx.x * BM;
    const size_t base = (size_t)bh * SEQ * HD;
    const float LSCALE = 0.0078125f;  // 1/128

    // ldmatrix address patterns
    // K (non-trans): rows = tokens (n), 16B chunks along d (k)
    const int krow = (group >> 1) * 8 + lr;   // token offset within 16-n block
    const int kcol = (group & 1) * 8;         // d offset within 16-k block
    // V (trans): rows = tokens (k), 16B chunks along d (n)
    const int vrow = (group & 1) * 8 + lr;    // token offset within 16-k block
    const int vcol = (group >> 1) * 8;        // d offset within 16-n block

    const uint32_t sk_b  = smem_u32(sk);
    const uint32_t svh_b = smem_u32(svh);
    const uint32_t svl_b = smem_u32(svl);

    load_2xm1<BM>(q + base + (size_t)m0 * HD, sq, tid);
    if (tid < HD) svs[tid] = g_vsum[bh * HD + tid];
    __syncthreads();

    // per-warp Q A-fragments: rows r1, r1+8, 4 k-steps over D=64
    const int r1 = w * 16 + g;
    uint32_t aq[4][4];
    #pragma unroll
    for (int j = 0; j < 4; ++j) {
        int k0 = j * 16 + qd * 2;
        aq[j][0] = *(const uint32_t*)&sq[r1 * ST + k0];
        aq[j][1] = *(const uint32_t*)&sq[(r1 + 8) * ST + k0];
        aq[j][2] = *(const uint32_t*)&sq[r1 * ST + k0 + 8];
        aq[j][3] = *(const uint32_t*)&sq[(r1 + 8) * ST + k0 + 8];
    }

    // ---------------- pass 1: row sums of exp(sim/128) ----------------
    float rs0 = 0.f, rs1 = 0.f;
    for (int kb = 0; kb < SEQ / KT; ++kb) {
        __syncthreads();
        load_2xm1<KT>(k + base + (size_t)kb * KT * HD, sk, tid);
        __syncthreads();

        float S[8][4];
        #pragma unroll
        for (int nb = 0; nb < 8; ++nb) { S[nb][0]=0.f; S[nb][1]=0.f; S[nb][2]=0.f; S[nb][3]=0.f; }
        #pragma unroll
        for (int j = 0; j < 4; ++j) {
            #pragma unroll
            for (int nb2 = 0; nb2 < 4; ++nb2) {
                uint32_t b0, b1, b2, b3;
                ldsm_x4(b0, b1, b2, b3,
                        sk_b + 2u * (uint32_t)((nb2 * 16 + krow) * ST + j * 16 + kcol));
                mma_bf16(S[2 * nb2],     aq[j], b0, b1);
                mma_bf16(S[2 * nb2 + 1], aq[j], b2, b3);
            }
        }
        #pragma unroll
        for (int nb = 0; nb < 8; ++nb) {
            rs0 += __expf(S[nb][0] * LSCALE) + __expf(S[nb][1] * LSCALE);
            rs1 += __expf(S[nb][2] * LSCALE) + __expf(S[nb][3] * LSCALE);
        }
    }
    rs0 += __shfl_xor_sync(0xffffffffu, rs0, 1);
    rs0 += __shfl_xor_sync(0xffffffffu, rs0, 2);
    rs1 += __shfl_xor_sync(0xffffffffu, rs1, 1);
    rs1 += __shfl_xor_sync(0xffffffffu, rs1, 2);
    if (qd == 0) { srs[r1] = rs0; srs[r1 + 8] = rs1; }
    __syncthreads();
    const float inv0 = 1.f / srs[r1];
    const float inv1 = 1.f / srs[r1 + 8];

    // ---------------- pass 2: write score, accumulate (p-1)·V ----------------
    float O[8][4];
    #pragma unroll
    for (int nb = 0; nb < 8; ++nb) { O[nb][0]=0.f; O[nb][1]=0.f; O[nb][2]=0.f; O[nb][3]=0.f; }

    float* scr0 = outp + OUT_ELEMS + (size_t)bh * SEQ * SEQ + (size_t)(m0 + r1) * SEQ;
    float* scr1 = scr0 + (size_t)8 * SEQ;

    for (int kb = 0; kb < SEQ / KT; ++kb) {
        __syncthreads();
        load_2xm1<KT>(k + base + (size_t)kb * KT * HD, sk, tid);
        load_v(v + base + (size_t)kb * KT * HD, svh, svl, tid);
        __syncthreads();

        float S[8][4];
        #pragma unroll
        for (int nb = 0; nb < 8; ++nb) { S[nb][0]=0.f; S[nb][1]=0.f; S[nb][2]=0.f; S[nb][3]=0.f; }
        #pragma unroll
        for (int j = 0; j < 4; ++j) {
            #pragma unroll
            for (int nb2 = 0; nb2 < 4; ++nb2) {
                uint32_t b0, b1, b2, b3;
                ldsm_x4(b0, b1, b2, b3,
                        sk_b + 2u * (uint32_t)((nb2 * 16 + krow) * ST + j * 16 + kcol));
                mma_bf16(S[2 * nb2],     aq[j], b0, b1);
                mma_bf16(S[2 * nb2 + 1], aq[j], b2, b3);
            }
        }

        // exp, normalized score store, pack e = p-1 as fp16 A-fragments
        uint32_t ea[4][4];
        #pragma unroll
        for (int j = 0; j < 4; ++j) {
            float e[2][4];
            #pragma unroll
            for (int t = 0; t < 2; ++t) {
                int nb = 2 * j + t;
                float p0 = __expf(S[nb][0] * LSCALE);
                float p1 = __expf(S[nb][1] * LSCALE);
                float p2 = __expf(S[nb][2] * LSCALE);
                float p3 = __expf(S[nb][3] * LSCALE);
                int col = kb * KT + nb * 8 + qd * 2;
                *(float2*)&scr0[col] = make_float2(p0 * inv0, p1 * inv0);
                *(float2*)&scr1[col] = make_float2(p2 * inv1, p3 * inv1);
                e[t][0] = p0 - 1.f; e[t][1] = p1 - 1.f;
                e[t][2] = p2 - 1.f; e[t][3] = p3 - 1.f;
            }
            ea[j][0] = pack_h2(e[0][0], e[0][1]);
            ea[j][1] = pack_h2(e[0][2], e[0][3]);
            ea[j][2] = pack_h2(e[1][0], e[1][1]);
            ea[j][3] = pack_h2(e[1][2], e[1][3]);
        }

        // O += e · v_hi + e · v_lo
        #pragma unroll
        for (int j = 0; j < 4; ++j) {
            #pragma unroll
            for (int nb2 = 0; nb2 < 4; ++nb2) {
                uint32_t off = 2u * (uint32_t)((j * 16 + vrow) * ST + nb2 * 16 + vcol);
                uint32_t b0, b1, b2, b3;
                ldsm_x4_t(b0, b1, b2, b3, svh_b + off);
                mma_f16(O[2 * nb2],     ea[j], b0, b1);
                mma_f16(O[2 * nb2 + 1], ea[j], b2, b3);
                uint32_t c0, c1, c2, c3;
                ldsm_x4_t(c0, c1, c2, c3, svl_b + off);
                mma_f16(O[2 * nb2],     ea[j], c0, c1);
                mma_f16(O[2 * nb2 + 1], ea[j], c2, c3);
            }
        }
    }

    // out = (vsum + O) / rowsum
    #pragma unroll
    for (int nb = 0; nb < 8; ++nb) {
        int d0 = nb * 8 + qd * 2;
        float vs0 = svs[d0], vs1 = svs[d0 + 1];
        float2 o0 = make_float2((O[nb][0] + vs0) * inv0, (O[nb][1] + vs1) * inv0);
        float2 o1 = make_float2((O[nb][2] + vs0) * inv1, (O[nb][3] + vs1) * inv1);
        *(float2*)&outp[base + (size_t)(m0 + r1) * HD + d0]     = o0;
        *(float2*)&outp[base + (size_t)(m0 + r1 + 8) * HD + d0] = o1;
    }
}

extern "C" void kernel_launch(void* const* d_in, const int* in_sizes, int n_in,
                              void* d_out, int out_size) {
    const float* q = (const float*)d_in[0];
    const float* k = (const float*)d_in[1];
    const float* v = (const float*)d_in[2];
    float* o = (float*)d_out;

    hd_vsum_kernel<<<BHD, 1024>>>(v);
    dim3 grid(SEQ / BM, BHD);
    hd_attn_kernel<<<grid, 256>>>(q, k, v, o);
}

// round 3
// speedup vs baseline: 2.5712x; 1.1746x over previous
#include <cuda_runtime.h>
#include <cuda_fp16.h>
#include <cuda_bf16.h>
#include <cstdint>

#define BHD 32       // B*H
#define SEQ 2048     // N
#define HD  64       // D
#define BM  128      // q rows per CTA (4 warps x 32 rows)
#define KT  64       // key tokens per tile
#define ST  72       // smem row stride in halves (conflict-free ldmatrix)

#define OUT_ELEMS ((size_t)BHD * SEQ * HD)

__device__ float g_vsum[BHD * HD];

// ---------------- vsum: per-(b,h) column sums of v ----------------
__global__ __launch_bounds__(1024)
void hd_vsum_kernel(const float* __restrict__ v) {
    __shared__ float red[16][64];
    int bh = blockIdx.x;
    int d = threadIdx.x & 63;
    int s = threadIdx.x >> 6;    // 0..15
    const float* vp = v + (size_t)bh * SEQ * HD + (size_t)s * 128 * HD + d;
    float acc = 0.f;
    #pragma unroll 8
    for (int t = 0; t < 128; ++t) acc += vp[t * HD];
    red[s][d] = acc;
    __syncthreads();
    if (threadIdx.x < 64) {
        float r = 0.f;
        #pragma unroll
        for (int i = 0; i < 16; ++i) r += red[i][threadIdx.x];
        g_vsum[bh * HD + threadIdx.x] = r;
    }
}

// ---------------- mma / ldmatrix helpers ----------------
__device__ __forceinline__ void mma_bf16(float* c, const uint32_t a[4], uint32_t b0, uint32_t b1) {
    asm volatile(
        "mma.sync.aligned.m16n8k16.row.col.f32.bf16.bf16.f32 "
        "{%0,%1,%2,%3},{%4,%5,%6,%7},{%8,%9},{%0,%1,%2,%3};\n"
        : "+f"(c[0]), "+f"(c[1]), "+f"(c[2]), "+f"(c[3])
        : "r"(a[0]), "r"(a[1]), "r"(a[2]), "r"(a[3]), "r"(b0), "r"(b1));
}
__device__ __forceinline__ void mma_f16(float* c, const uint32_t a[4], uint32_t b0, uint32_t b1) {
    asm volatile(
        "mma.sync.aligned.m16n8k16.row.col.f32.f16.f16.f32 "
        "{%0,%1,%2,%3},{%4,%5,%6,%7},{%8,%9},{%0,%1,%2,%3};\n"
        : "+f"(c[0]), "+f"(c[1]), "+f"(c[2]), "+f"(c[3])
        : "r"(a[0]), "r"(a[1]), "r"(a[2]), "r"(a[3]), "r"(b0), "r"(b1));
}
__device__ __forceinline__ void ldsm_x4(uint32_t& r0, uint32_t& r1, uint32_t& r2, uint32_t& r3, uint32_t a) {
    asm volatile("ldmatrix.sync.aligned.m8n8.x4.shared.b16 {%0,%1,%2,%3}, [%4];\n"
        : "=r"(r0), "=r"(r1), "=r"(r2), "=r"(r3) : "r"(a));
}
__device__ __forceinline__ void ldsm_x4_t(uint32_t& r0, uint32_t& r1, uint32_t& r2, uint32_t& r3, uint32_t a) {
    asm volatile("ldmatrix.sync.aligned.m8n8.x4.trans.shared.b16 {%0,%1,%2,%3}, [%4];\n"
        : "=r"(r0), "=r"(r1), "=r"(r2), "=r"(r3) : "r"(a));
}
__device__ __forceinline__ uint32_t smem_u32(const void* p) {
    return (uint32_t)__cvta_generic_to_shared(p);
}
__device__ __forceinline__ uint32_t pack_h2(float a, float b) {
    __half2 h = __floats2half2_rn(a, b);
    return *(uint32_t*)&h;
}

// load ROWSx64 fp32 tile, apply 2x-1, store bf16 (stride ST), 128 threads
template<int ROWS>
__device__ __forceinline__ void load_2xm1(const float* __restrict__ gsrc,
                                          __nv_bfloat16* __restrict__ dst, int tid) {
    const float4* g4 = (const float4*)gsrc;
    #pragma unroll
    for (int i = 0; i < ROWS / 8; ++i) {
        int f = i * 128 + tid;
        int r = f >> 4;
        int c = (f & 15) << 2;
        float4 x = g4[f];
        __nv_bfloat162 ab, cd;
        ab.x = __float2bfloat16(2.f * x.x - 1.f);
        ab.y = __float2bfloat16(2.f * x.y - 1.f);
        cd.x = __float2bfloat16(2.f * x.z - 1.f);
        cd.y = __float2bfloat16(2.f * x.w - 1.f);
        *(__nv_bfloat162*)&dst[r * ST + c]     = ab;
        *(__nv_bfloat162*)&dst[r * ST + c + 2] = cd;
    }
}

// load 64x64 fp32 V tile -> fp16 (stride ST), [token][d], 128 threads
__device__ __forceinline__ void load_v(const float* __restrict__ gsrc,
                                       half* __restrict__ dh, int tid) {
    const float4* g4 = (const float4*)gsrc;
    #pragma unroll
    for (int i = 0; i < 8; ++i) {
        int f = i * 128 + tid;
        int r = f >> 4;
        int c = (f & 15) << 2;
        float4 x = g4[f];
        *(half2*)&dh[r * ST + c]     = __floats2half2_rn(x.x, x.y);
        *(half2*)&dh[r * ST + c + 2] = __floats2half2_rn(x.z, x.w);
    }
}

__global__ __launch_bounds__(128, 2)
void hd_attn_kernel(const float* __restrict__ q, const float* __restrict__ k,
                    const float* __restrict__ v, float* __restrict__ outp) {
    __shared__ __nv_bfloat16 sq[BM * ST];
    __shared__ __nv_bfloat16 sk[KT * ST];
    __shared__ half svh[KT * ST];
    __shared__ float srs[BM];
    __shared__ float svs[HD];

    const int tid = threadIdx.x;
    const int w = tid >> 5;
    const int lane = tid & 31;
    const int g = lane >> 2;          // 0..7
    const int qd = lane & 3;          // 0..3
    const int group = lane >> 3;      // 0..3 (ldmatrix address group)
    const int lr = lane & 7;
    const int bh = blockIdx.y;
    const int m0 = blockIdx.x * BM;
    const size_t base = (size_t)bh * SEQ * HD;
    const float LSCALE = 0.0078125f;  // 1/128

    // ldmatrix address patterns
    const int krow = (group >> 1) * 8 + lr;   // K non-trans
    const int kcol = (group & 1) * 8;
    const int vrow = (group & 1) * 8 + lr;    // V trans
    const int vcol = (group >> 1) * 8;

    const uint32_t sk_b  = smem_u32(sk);
    const uint32_t svh_b = smem_u32(svh);

    load_2xm1<BM>(q + base + (size_t)m0 * HD, sq, tid);
    if (tid < HD) svs[tid] = g_vsum[bh * HD + tid];
    __syncthreads();

    // per-warp Q A-fragments: 32 rows per warp = 2 row-blocks of 16
    const int r1 = w * 32 + g;   // block0 rows: r1, r1+8; block1: r1+16, r1+24
    uint32_t aq[4][8];
    #pragma unroll
    for (int j = 0; j < 4; ++j) {
        int k0 = j * 16 + qd * 2;
        aq[j][0] = *(const uint32_t*)&sq[r1 * ST + k0];
        aq[j][1] = *(const uint32_t*)&sq[(r1 + 8) * ST + k0];
        aq[j][2] = *(const uint32_t*)&sq[r1 * ST + k0 + 8];
        aq[j][3] = *(const uint32_t*)&sq[(r1 + 8) * ST + k0 + 8];
        aq[j][4] = *(const uint32_t*)&sq[(r1 + 16) * ST + k0];
        aq[j][5] = *(const uint32_t*)&sq[(r1 + 24) * ST + k0];
        aq[j][6] = *(const uint32_t*)&sq[(r1 + 16) * ST + k0 + 8];
        aq[j][7] = *(const uint32_t*)&sq[(r1 + 24) * ST + k0 + 8];
    }

    // ---------------- pass 1: row sums of exp(sim/128) ----------------
    float rs[4] = {0.f, 0.f, 0.f, 0.f};
    for (int kb = 0; kb < SEQ / KT; ++kb) {
        __syncthreads();
        load_2xm1<KT>(k + base + (size_t)kb * KT * HD, sk, tid);
        __syncthreads();

        float S[2][8][4];
        #pragma unroll
        for (int blk = 0; blk < 2; ++blk)
            #pragma unroll
            for (int nb = 0; nb < 8; ++nb)
                { S[blk][nb][0]=0.f; S[blk][nb][1]=0.f; S[blk][nb][2]=0.f; S[blk][nb][3]=0.f; }
        #pragma unroll
        for (int j = 0; j < 4; ++j) {
            #pragma unroll
            for (int nb2 = 0; nb2 < 4; ++nb2) {
                uint32_t b0, b1, b2, b3;
                ldsm_x4(b0, b1, b2, b3,
                        sk_b + 2u * (uint32_t)((nb2 * 16 + krow) * ST + j * 16 + kcol));
                mma_bf16(S[0][2*nb2],   &aq[j][0], b0, b1);
                mma_bf16(S[0][2*nb2+1], &aq[j][0], b2, b3);
                mma_bf16(S[1][2*nb2],   &aq[j][4], b0, b1);
                mma_bf16(S[1][2*nb2+1], &aq[j][4], b2, b3);
            }
        }
        #pragma unroll
        for (int blk = 0; blk < 2; ++blk)
            #pragma unroll
            for (int nb = 0; nb < 8; ++nb) {
                rs[2*blk]   += __expf(S[blk][nb][0] * LSCALE) + __expf(S[blk][nb][1] * LSCALE);
                rs[2*blk+1] += __expf(S[blk][nb][2] * LSCALE) + __expf(S[blk][nb][3] * LSCALE);
            }
    }
    #pragma unroll
    for (int i = 0; i < 4; ++i) {
        rs[i] += __shfl_xor_sync(0xffffffffu, rs[i], 1);
        rs[i] += __shfl_xor_sync(0xffffffffu, rs[i], 2);
    }
    if (qd == 0) {
        srs[r1] = rs[0]; srs[r1 + 8] = rs[1];
        srs[r1 + 16] = rs[2]; srs[r1 + 24] = rs[3];
    }
    __syncthreads();
    float inv[4];
    inv[0] = 1.f / srs[r1];      inv[1] = 1.f / srs[r1 + 8];
    inv[2] = 1.f / srs[r1 + 16]; inv[3] = 1.f / srs[r1 + 24];

    // ---------------- pass 2: write score, accumulate (p-1)·V ----------------
    float O[2][8][4];
    #pragma unroll
    for (int blk = 0; blk < 2; ++blk)
        #pragma unroll
        for (int nb = 0; nb < 8; ++nb)
            { O[blk][nb][0]=0.f; O[blk][nb][1]=0.f; O[blk][nb][2]=0.f; O[blk][nb][3]=0.f; }

    float* scr = outp + OUT_ELEMS + (size_t)bh * SEQ * SEQ + (size_t)(m0 + r1) * SEQ;
    // row offsets (in floats): 0, 8*SEQ, 16*SEQ, 24*SEQ

    for (int kb = 0; kb < SEQ / KT; ++kb) {
        __syncthreads();
        load_2xm1<KT>(k + base + (size_t)kb * KT * HD, sk, tid);
        load_v(v + base + (size_t)kb * KT * HD, svh, tid);
        __syncthreads();

        float S[2][8][4];
        #pragma unroll
        for (int blk = 0; blk < 2; ++blk)
            #pragma unroll
            for (int nb = 0; nb < 8; ++nb)
                { S[blk][nb][0]=0.f; S[blk][nb][1]=0.f; S[blk][nb][2]=0.f; S[blk][nb][3]=0.f; }
        #pragma unroll
        for (int j = 0; j < 4; ++j) {
            #pragma unroll
            for (int nb2 = 0; nb2 < 4; ++nb2) {
                uint32_t b0, b1, b2, b3;
                ldsm_x4(b0, b1, b2, b3,
                        sk_b + 2u * (uint32_t)((nb2 * 16 + krow) * ST + j * 16 + kcol));
                mma_bf16(S[0][2*nb2],   &aq[j][0], b0, b1);
                mma_bf16(S[0][2*nb2+1], &aq[j][0], b2, b3);
                mma_bf16(S[1][2*nb2],   &aq[j][4], b0, b1);
                mma_bf16(S[1][2*nb2+1], &aq[j][4], b2, b3);
            }
        }

        // exp, normalized score store, pack e = p-1 as fp16 A-fragments
        uint32_t ea[2][4][4];
        #pragma unroll
        for (int blk = 0; blk < 2; ++blk) {
            #pragma unroll
            for (int j = 0; j < 4; ++j) {
                #pragma unroll
                for (int t = 0; t < 2; ++t) {
                    int nb = 2 * j + t;
                    float p0 = __expf(S[blk][nb][0] * LSCALE);
                    float p1 = __expf(S[blk][nb][1] * LSCALE);
                    float p2 = __expf(S[blk][nb][2] * LSCALE);
                    float p3 = __expf(S[blk][nb][3] * LSCALE);
                    int col = kb * KT + nb * 8 + qd * 2;
                    size_t ro = (size_t)(blk * 16) * SEQ;
                    *(float2*)&scr[ro + col] =
                        make_float2(p0 * inv[2*blk], p1 * inv[2*blk]);
                    *(float2*)&scr[ro + (size_t)8 * SEQ + col] =
                        make_float2(p2 * inv[2*blk+1], p3 * inv[2*blk+1]);
                    ea[blk][j][t*2]   = pack_h2(p0 - 1.f, p1 - 1.f);
                    ea[blk][j][t*2+1] = pack_h2(p2 - 1.f, p3 - 1.f);
                }
            }
        }

        // O += e · v
        #pragma unroll
        for (int j = 0; j < 4; ++j) {
            #pragma unroll
            for (int nb2 = 0; nb2 < 4; ++nb2) {
                uint32_t b0, b1, b2, b3;
                ldsm_x4_t(b0, b1, b2, b3,
                          svh_b + 2u * (uint32_t)((j * 16 + vrow) * ST + nb2 * 16 + vcol));
                mma_f16(O[0][2*nb2],   ea[0][j], b0, b1);
                mma_f16(O[0][2*nb2+1], ea[0][j], b2, b3);
                mma_f16(O[1][2*nb2],   ea[1][j], b0, b1);
                mma_f16(O[1][2*nb2+1], ea[1][j], b2, b3);
            }
        }
    }

    // out = (vsum + O) / rowsum
    #pragma unroll
    for (int blk = 0; blk < 2; ++blk) {
        #pragma unroll
        for (int nb = 0; nb < 8; ++nb) {
            int d0 = nb * 8 + qd * 2;
            float vs0 = svs[d0], vs1 = svs[d0 + 1];
            float2 o0 = make_float2((O[blk][nb][0] + vs0) * inv[2*blk],
                                    (O[blk][nb][1] + vs1) * inv[2*blk]);
            float2 o1 = make_float2((O[blk][nb][2] + vs0) * inv[2*blk+1],
                                    (O[blk][nb][3] + vs1) * inv[2*blk+1]);
            int r = m0 + r1 + blk * 16;
            *(float2*)&outp[base + (size_t)r * HD + d0]       = o0;
            *(float2*)&outp[base + (size_t)(r + 8) * HD + d0] = o1;
        }
    }
}

extern "C" void kernel_launch(void* const* d_in, const int* in_sizes, int n_in,
                              void* d_out, int out_size) {
    const float* q = (const float*)d_in[0];
    const float* k = (const float*)d_in[1];
    const float* v = (const float*)d_in[2];
    float* o = (float*)d_out;

    hd_vsum_kernel<<<BHD, 1024>>>(v);
    dim3 grid(SEQ / BM, BHD);
    hd_attn_kernel<<<grid, 128>>>(q, k, v, o);
}

// round 4
// speedup vs baseline: 3.1276x; 1.2164x over previous
#include <cuda_runtime.h>
#include <cuda_fp16.h>
#include <cuda_bf16.h>
#include <cstdint>

#define BHD 32       // B*H
#define SEQ 2048     // N
#define HD  64       // D
#define BM  128      // q rows per CTA (4 warps x 32 rows)
#define KT  64       // key tokens per tile
#define ST  72       // smem row stride in halves (conflict-free ldmatrix)
#define TILE_B (KT * ST * 2)                 // 9216 bytes per staged tile

#define OUT_ELEMS ((size_t)BHD * SEQ * HD)
#define TOT ((size_t)BHD * SEQ * HD)

__device__ float g_vsum[BHD * HD];
__device__ __align__(16) __nv_bfloat16 g_qc[TOT];   // bf16(2q-1)
__device__ __align__(16) __nv_bfloat16 g_kc[TOT];   // bf16(2k-1)
__device__ __align__(16) half          g_vc[TOT];   // fp16(v)

// ---------------- pre-convert: q,k -> bf16(2x-1), v -> fp16 ----------------
__global__ __launch_bounds__(512)
void hd_convert_kernel(const float4* __restrict__ q, const float4* __restrict__ k,
                       const float4* __restrict__ v) {
    size_t i = (size_t)blockIdx.x * 512 + threadIdx.x;   // < TOT/4
    __nv_bfloat162* qo = (__nv_bfloat162*)g_qc;
    __nv_bfloat162* ko = (__nv_bfloat162*)g_kc;
    half2* vo = (half2*)g_vc;

    float4 xq = q[i];
    __nv_bfloat162 a, b;
    a.x = __float2bfloat16(2.f * xq.x - 1.f); a.y = __float2bfloat16(2.f * xq.y - 1.f);
    b.x = __float2bfloat16(2.f * xq.z - 1.f); b.y = __float2bfloat16(2.f * xq.w - 1.f);
    qo[2 * i] = a; qo[2 * i + 1] = b;

    float4 xk = k[i];
    a.x = __float2bfloat16(2.f * xk.x - 1.f); a.y = __float2bfloat16(2.f * xk.y - 1.f);
    b.x = __float2bfloat16(2.f * xk.z - 1.f); b.y = __float2bfloat16(2.f * xk.w - 1.f);
    ko[2 * i] = a; ko[2 * i + 1] = b;

    float4 xv = v[i];
    vo[2 * i]     = __floats2half2_rn(xv.x, xv.y);
    vo[2 * i + 1] = __floats2half2_rn(xv.z, xv.w);
}

// ---------------- vsum: per-(b,h) column sums of v ----------------
__global__ __launch_bounds__(1024)
void hd_vsum_kernel(const float* __restrict__ v) {
    __shared__ float red[16][64];
    int bh = blockIdx.x;
    int d = threadIdx.x & 63;
    int s = threadIdx.x >> 6;
    const float* vp = v + (size_t)bh * SEQ * HD + (size_t)s * 128 * HD + d;
    float acc = 0.f;
    #pragma unroll 8
    for (int t = 0; t < 128; ++t) acc += vp[t * HD];
    red[s][d] = acc;
    __syncthreads();
    if (threadIdx.x < 64) {
        float r = 0.f;
        #pragma unroll
        for (int i = 0; i < 16; ++i) r += red[i][threadIdx.x];
        g_vsum[bh * HD + threadIdx.x] = r;
    }
}

// ---------------- mma / ldmatrix / cp.async helpers ----------------
__device__ __forceinline__ void mma_bf16(float* c, const uint32_t a[4], uint32_t b0, uint32_t b1) {
    asm volatile(
        "mma.sync.aligned.m16n8k16.row.col.f32.bf16.bf16.f32 "
        "{%0,%1,%2,%3},{%4,%5,%6,%7},{%8,%9},{%0,%1,%2,%3};\n"
        : "+f"(c[0]), "+f"(c[1]), "+f"(c[2]), "+f"(c[3])
        : "r"(a[0]), "r"(a[1]), "r"(a[2]), "r"(a[3]), "r"(b0), "r"(b1));
}
__device__ __forceinline__ void mma_f16(float* c, const uint32_t a[4], uint32_t b0, uint32_t b1) {
    asm volatile(
        "mma.sync.aligned.m16n8k16.row.col.f32.f16.f16.f32 "
        "{%0,%1,%2,%3},{%4,%5,%6,%7},{%8,%9},{%0,%1,%2,%3};\n"
        : "+f"(c[0]), "+f"(c[1]), "+f"(c[2]), "+f"(c[3])
        : "r"(a[0]), "r"(a[1]), "r"(a[2]), "r"(a[3]), "r"(b0), "r"(b1));
}
__device__ __forceinline__ void ldsm_x4(uint32_t& r0, uint32_t& r1, uint32_t& r2, uint32_t& r3, uint32_t a) {
    asm volatile("ldmatrix.sync.aligned.m8n8.x4.shared.b16 {%0,%1,%2,%3}, [%4];\n"
        : "=r"(r0), "=r"(r1), "=r"(r2), "=r"(r3) : "r"(a));
}
__device__ __forceinline__ void ldsm_x4_t(uint32_t& r0, uint32_t& r1, uint32_t& r2, uint32_t& r3, uint32_t a) {
    asm volatile("ldmatrix.sync.aligned.m8n8.x4.trans.shared.b16 {%0,%1,%2,%3}, [%4];\n"
        : "=r"(r0), "=r"(r1), "=r"(r2), "=r"(r3) : "r"(a));
}
__device__ __forceinline__ uint32_t smem_u32(const void* p) {
    return (uint32_t)__cvta_generic_to_shared(p);
}
__device__ __forceinline__ uint32_t pack_h2(float a, float b) {
    __half2 h = __floats2half2_rn(a, b);
    return *(uint32_t*)&h;
}
__device__ __forceinline__ void cp16(uint32_t dst, const void* src) {
    asm volatile("cp.async.cg.shared.global [%0], [%1], 16;\n" :: "r"(dst), "l"(src));
}
__device__ __forceinline__ void cp_commit() {
    asm volatile("cp.async.commit_group;\n");
}
template<int N>
__device__ __forceinline__ void cp_wait() {
    asm volatile("cp.async.wait_group %0;\n" :: "n"(N));
}

// issue one 64x64 16-bit tile (row = 128B) into smem (byte stride 144), 128 threads
__device__ __forceinline__ void issue_tile(uint32_t sdst, const void* gsrc, int tid) {
    #pragma unroll
    for (int i = 0; i < 4; ++i) {
        int idx = i * 128 + tid;
        int r = idx >> 3, c = idx & 7;
        cp16(sdst + (uint32_t)(r * (ST * 2) + c * 16), (const char*)gsrc + r * 128 + c * 16);
    }
}

// QK tile: S[2][8][4] += Aq * K^T
__device__ __forceinline__ void qk_tile(uint32_t sk_b, const uint32_t aq[4][8],
                                        int krow, int kcol, float S[2][8][4]) {
    #pragma unroll
    for (int blk = 0; blk < 2; ++blk)
        #pragma unroll
        for (int nb = 0; nb < 8; ++nb)
            { S[blk][nb][0]=0.f; S[blk][nb][1]=0.f; S[blk][nb][2]=0.f; S[blk][nb][3]=0.f; }
    #pragma unroll
    for (int j = 0; j < 4; ++j) {
        #pragma unroll
        for (int nb2 = 0; nb2 < 4; ++nb2) {
            uint32_t b0, b1, b2, b3;
            ldsm_x4(b0, b1, b2, b3,
                    sk_b + 2u * (uint32_t)((nb2 * 16 + krow) * ST + j * 16 + kcol));
            mma_bf16(S[0][2*nb2],   &aq[j][0], b0, b1);
            mma_bf16(S[0][2*nb2+1], &aq[j][0], b2, b3);
            mma_bf16(S[1][2*nb2],   &aq[j][4], b0, b1);
            mma_bf16(S[1][2*nb2+1], &aq[j][4], b2, b3);
        }
    }
}

__global__ __launch_bounds__(128, 2)
void hd_attn_kernel(float* __restrict__ outp) {
    __shared__ __align__(16) char pool[4 * TILE_B];   // 36864 B
    __shared__ float srs[BM];
    __shared__ float svs[HD];

    const int tid = threadIdx.x;
    const int w = tid >> 5;
    const int lane = tid & 31;
    const int g = lane >> 2;
    const int qd = lane & 3;
    const int group = lane >> 3;
    const int lr = lane & 7;
    const int bh = blockIdx.y;
    const int m0 = blockIdx.x * BM;
    const size_t base = (size_t)bh * SEQ * HD;
    const float LSCALE = 0.0078125f;  // 1/128

    const int krow = (group >> 1) * 8 + lr;
    const int kcol = (group & 1) * 8;
    const int vrow = (group & 1) * 8 + lr;
    const int vcol = (group >> 1) * 8;

    const uint32_t pb = smem_u32(pool);
    const __nv_bfloat16* kg = g_kc + base;
    const half* vg = g_vc + base;

    // ---- stage Q (128 rows x 128B) into pool[0..2*TILE_B) and consume to regs ----
    {
        const char* qg = (const char*)(g_qc + base + (size_t)m0 * HD);
        #pragma unroll
        for (int i = 0; i < 8; ++i) {
            int idx = i * 128 + tid;
            int r = idx >> 3, c = idx & 7;
            cp16(pb + (uint32_t)(r * (ST * 2) + c * 16), qg + r * 128 + c * 16);
        }
        cp_commit();
    }
    if (tid < HD) svs[tid] = g_vsum[bh * HD + tid];
    cp_wait<0>();
    __syncthreads();

    const int r1 = w * 32 + g;
    uint32_t aq[4][8];
    {
        const __nv_bfloat16* sq = (const __nv_bfloat16*)pool;
        #pragma unroll
        for (int j = 0; j < 4; ++j) {
            int k0 = j * 16 + qd * 2;
            aq[j][0] = *(const uint32_t*)&sq[r1 * ST + k0];
            aq[j][1] = *(const uint32_t*)&sq[(r1 + 8) * ST + k0];
            aq[j][2] = *(const uint32_t*)&sq[r1 * ST + k0 + 8];
            aq[j][3] = *(const uint32_t*)&sq[(r1 + 8) * ST + k0 + 8];
            aq[j][4] = *(const uint32_t*)&sq[(r1 + 16) * ST + k0];
            aq[j][5] = *(const uint32_t*)&sq[(r1 + 24) * ST + k0];
            aq[j][6] = *(const uint32_t*)&sq[(r1 + 16) * ST + k0 + 8];
            aq[j][7] = *(const uint32_t*)&sq[(r1 + 24) * ST + k0 + 8];
        }
    }
    __syncthreads();

    // ---------------- pass 1: row sums, 4-deep K pipeline ----------------
    #pragma unroll
    for (int t = 0; t < 3; ++t) {
        issue_tile(pb + t * TILE_B, kg + (size_t)t * KT * HD, tid);
        cp_commit();
    }

    float rs[4] = {0.f, 0.f, 0.f, 0.f};
    for (int kb = 0; kb < SEQ / KT; ++kb) {
        if (kb + 3 < SEQ / KT)
            issue_tile(pb + ((kb + 3) & 3) * TILE_B, kg + (size_t)(kb + 3) * KT * HD, tid);
        cp_commit();
        cp_wait<3>();
        __syncthreads();

        float S[2][8][4];
        qk_tile(pb + (kb & 3) * TILE_B, aq, krow, kcol, S);
        #pragma unroll
        for (int blk = 0; blk < 2; ++blk)
            #pragma unroll
            for (int nb = 0; nb < 8; ++nb) {
                rs[2*blk]   += __expf(S[blk][nb][0] * LSCALE) + __expf(S[blk][nb][1] * LSCALE);
                rs[2*blk+1] += __expf(S[blk][nb][2] * LSCALE) + __expf(S[blk][nb][3] * LSCALE);
            }
        __syncthreads();
    }
    #pragma unroll
    for (int i = 0; i < 4; ++i) {
        rs[i] += __shfl_xor_sync(0xffffffffu, rs[i], 1);
        rs[i] += __shfl_xor_sync(0xffffffffu, rs[i], 2);
    }
    if (qd == 0) {
        srs[r1] = rs[0]; srs[r1 + 8] = rs[1];
        srs[r1 + 16] = rs[2]; srs[r1 + 24] = rs[3];
    }
    __syncthreads();
    float inv[4];
    inv[0] = 1.f / srs[r1];      inv[1] = 1.f / srs[r1 + 8];
    inv[2] = 1.f / srs[r1 + 16]; inv[3] = 1.f / srs[r1 + 24];

    // ---------------- pass 2: 2-deep K+V pipeline ----------------
    float O[2][8][4];
    #pragma unroll
    for (int blk = 0; blk < 2; ++blk)
        #pragma unroll
        for (int nb = 0; nb < 8; ++nb)
            { O[blk][nb][0]=0.f; O[blk][nb][1]=0.f; O[blk][nb][2]=0.f; O[blk][nb][3]=0.f; }

    float* scr = outp + OUT_ELEMS + (size_t)bh * SEQ * SEQ + (size_t)(m0 + r1) * SEQ;

    // buffers: K -> pool[0],pool[1]; V -> pool[2],pool[3]
    issue_tile(pb,              kg, tid);
    issue_tile(pb + 2 * TILE_B, vg, tid);
    cp_commit();

    for (int kb = 0; kb < SEQ / KT; ++kb) {
        if (kb + 1 < SEQ / KT) {
            int nb1 = (kb + 1) & 1;
            issue_tile(pb + nb1 * TILE_B,       kg + (size_t)(kb + 1) * KT * HD, tid);
            issue_tile(pb + (2 + nb1) * TILE_B, vg + (size_t)(kb + 1) * KT * HD, tid);
        }
        cp_commit();
        cp_wait<1>();
        __syncthreads();

        const uint32_t sk_b  = pb + (kb & 1) * TILE_B;
        const uint32_t svh_b = pb + (2 + (kb & 1)) * TILE_B;

        float S[2][8][4];
        qk_tile(sk_b, aq, krow, kcol, S);

        uint32_t ea[2][4][4];
        #pragma unroll
        for (int blk = 0; blk < 2; ++blk) {
            #pragma unroll
            for (int j = 0; j < 4; ++j) {
                #pragma unroll
                for (int t = 0; t < 2; ++t) {
                    int nb = 2 * j + t;
                    float p0 = __expf(S[blk][nb][0] * LSCALE);
                    float p1 = __expf(S[blk][nb][1] * LSCALE);
                    float p2 = __expf(S[blk][nb][2] * LSCALE);
                    float p3 = __expf(S[blk][nb][3] * LSCALE);
                    int col = kb * KT + nb * 8 + qd * 2;
                    size_t ro = (size_t)(blk * 16) * SEQ;
                    __stcs((float2*)&scr[ro + col],
                           make_float2(p0 * inv[2*blk], p1 * inv[2*blk]));
                    __stcs((float2*)&scr[ro + (size_t)8 * SEQ + col],
                           make_float2(p2 * inv[2*blk+1], p3 * inv[2*blk+1]));
                    ea[blk][j][t*2]   = pack_h2(p0 - 1.f, p1 - 1.f);
                    ea[blk][j][t*2+1] = pack_h2(p2 - 1.f, p3 - 1.f);
                }
            }
        }

        #pragma unroll
        for (int j = 0; j < 4; ++j) {
            #pragma unroll
            for (int nb2 = 0; nb2 < 4; ++nb2) {
                uint32_t b0, b1, b2, b3;
                ldsm_x4_t(b0, b1, b2, b3,
                          svh_b + 2u * (uint32_t)((j * 16 + vrow) * ST + nb2 * 16 + vcol));
                mma_f16(O[0][2*nb2],   ea[0][j], b0, b1);
                mma_f16(O[0][2*nb2+1], ea[0][j], b2, b3);
                mma_f16(O[1][2*nb2],   ea[1][j], b0, b1);
                mma_f16(O[1][2*nb2+1], ea[1][j], b2, b3);
            }
        }
        __syncthreads();
    }

    // out = (vsum + O) / rowsum
    #pragma unroll
    for (int blk = 0; blk < 2; ++blk) {
        #pragma unroll
        for (int nb = 0; nb < 8; ++nb) {
            int d0 = nb * 8 + qd * 2;
            float vs0 = svs[d0], vs1 = svs[d0 + 1];
            float2 o0 = make_float2((O[blk][nb][0] + vs0) * inv[2*blk],
                                    (O[blk][nb][1] + vs1) * inv[2*blk]);
            float2 o1 = make_float2((O[blk][nb][2] + vs0) * inv[2*blk+1],
                                    (O[blk][nb][3] + vs1) * inv[2*blk+1]);
            int r = m0 + r1 + blk * 16;
            __stcs((float2*)&outp[base + (size_t)r * HD + d0], o0);
            __stcs((float2*)&outp[base + (size_t)(r + 8) * HD + d0], o1);
        }
    }
}

extern "C" void kernel_launch(void* const* d_in, const int* in_sizes, int n_in,
                              void* d_out, int out_size) {
    const float* q = (const float*)d_in[0];
    const float* k = (const float*)d_in[1];
    const float* v = (const float*)d_in[2];
    float* o = (float*)d_out;

    hd_convert_kernel<<<(int)(TOT / 4 / 512), 512>>>((const float4*)q, (const float4*)k,
                                                     (const float4*)v);
    hd_vsum_kernel<<<BHD, 1024>>>(v);
    dim3 grid(SEQ / BM, BHD);
    hd_attn_kernel<<<grid, 128>>>(o);
}

// round 5
// speedup vs baseline: 3.2897x; 1.0518x over previous
#include <cuda_runtime.h>
#include <cuda_fp16.h>
#include <cuda_bf16.h>
#include <cstdint>

#define BHD 32       // B*H
#define SEQ 2048     // N
#define HD  64       // D
#define BM  128      // q rows per CTA (4 warps x 32 rows)
#define KT  64       // key tokens per tile
#define ST  72       // smem row stride in halves (conflict-free ldmatrix)
#define TILE_B (KT * ST * 2)                 // 9216 bytes per staged tile

#define OUT_ELEMS ((size_t)BHD * SEQ * HD)
#define TOT ((size_t)BHD * SEQ * HD)

__device__ float g_vsum[BHD * HD];
__device__ __align__(16) __nv_bfloat16 g_qc[TOT];   // bf16(2q-1)
__device__ __align__(16) __nv_bfloat16 g_kc[TOT];   // bf16(2k-1)
__device__ __align__(16) half          g_vc[TOT];   // fp16(v)

// ---------------- pre-convert: q,k -> bf16(2x-1), v -> fp16 ----------------
__global__ __launch_bounds__(512)
void hd_convert_kernel(const float4* __restrict__ q, const float4* __restrict__ k,
                       const float4* __restrict__ v) {
    size_t i = (size_t)blockIdx.x * 512 + threadIdx.x;   // < TOT/4
    __nv_bfloat162* qo = (__nv_bfloat162*)g_qc;
    __nv_bfloat162* ko = (__nv_bfloat162*)g_kc;
    half2* vo = (half2*)g_vc;

    float4 xq = q[i];
    __nv_bfloat162 a, b;
    a.x = __float2bfloat16(2.f * xq.x - 1.f); a.y = __float2bfloat16(2.f * xq.y - 1.f);
    b.x = __float2bfloat16(2.f * xq.z - 1.f); b.y = __float2bfloat16(2.f * xq.w - 1.f);
    qo[2 * i] = a; qo[2 * i + 1] = b;

    float4 xk = k[i];
    a.x = __float2bfloat16(2.f * xk.x - 1.f); a.y = __float2bfloat16(2.f * xk.y - 1.f);
    b.x = __float2bfloat16(2.f * xk.z - 1.f); b.y = __float2bfloat16(2.f * xk.w - 1.f);
    ko[2 * i] = a; ko[2 * i + 1] = b;

    float4 xv = v[i];
    vo[2 * i]     = __floats2half2_rn(xv.x, xv.y);
    vo[2 * i + 1] = __floats2half2_rn(xv.z, xv.w);
}

// ---------------- vsum: per-(b,h) column sums of v ----------------
__global__ __launch_bounds__(1024)
void hd_vsum_kernel(const float* __restrict__ v) {
    __shared__ float red[16][64];
    int bh = blockIdx.x;
    int d = threadIdx.x & 63;
    int s = threadIdx.x >> 6;
    const float* vp = v + (size_t)bh * SEQ * HD + (size_t)s * 128 * HD + d;
    float acc = 0.f;
    #pragma unroll 8
    for (int t = 0; t < 128; ++t) acc += vp[t * HD];
    red[s][d] = acc;
    __syncthreads();
    if (threadIdx.x < 64) {
        float r = 0.f;
        #pragma unroll
        for (int i = 0; i < 16; ++i) r += red[i][threadIdx.x];
        g_vsum[bh * HD + threadIdx.x] = r;
    }
}

// ---------------- mma / ldmatrix / cp.async helpers ----------------
__device__ __forceinline__ void mma_bf16(float* c, const uint32_t a[4], uint32_t b0, uint32_t b1) {
    asm volatile(
        "mma.sync.aligned.m16n8k16.row.col.f32.bf16.bf16.f32 "
        "{%0,%1,%2,%3},{%4,%5,%6,%7},{%8,%9},{%0,%1,%2,%3};\n"
        : "+f"(c[0]), "+f"(c[1]), "+f"(c[2]), "+f"(c[3])
        : "r"(a[0]), "r"(a[1]), "r"(a[2]), "r"(a[3]), "r"(b0), "r"(b1));
}
__device__ __forceinline__ void mma_f16(float* c, const uint32_t a[4], uint32_t b0, uint32_t b1) {
    asm volatile(
        "mma.sync.aligned.m16n8k16.row.col.f32.f16.f16.f32 "
        "{%0,%1,%2,%3},{%4,%5,%6,%7},{%8,%9},{%0,%1,%2,%3};\n"
        : "+f"(c[0]), "+f"(c[1]), "+f"(c[2]), "+f"(c[3])
        : "r"(a[0]), "r"(a[1]), "r"(a[2]), "r"(a[3]), "r"(b0), "r"(b1));
}
__device__ __forceinline__ void ldsm_x4(uint32_t& r0, uint32_t& r1, uint32_t& r2, uint32_t& r3, uint32_t a) {
    asm volatile("ldmatrix.sync.aligned.m8n8.x4.shared.b16 {%0,%1,%2,%3}, [%4];\n"
        : "=r"(r0), "=r"(r1), "=r"(r2), "=r"(r3) : "r"(a));
}
__device__ __forceinline__ void ldsm_x4_t(uint32_t& r0, uint32_t& r1, uint32_t& r2, uint32_t& r3, uint32_t a) {
    asm volatile("ldmatrix.sync.aligned.m8n8.x4.trans.shared.b16 {%0,%1,%2,%3}, [%4];\n"
        : "=r"(r0), "=r"(r1), "=r"(r2), "=r"(r3) : "r"(a));
}
__device__ __forceinline__ uint32_t smem_u32(const void* p) {
    return (uint32_t)__cvta_generic_to_shared(p);
}
__device__ __forceinline__ uint32_t pack_h2(float a, float b) {
    __half2 h = __floats2half2_rn(a, b);
    return *(uint32_t*)&h;
}
__device__ __forceinline__ void cp16(uint32_t dst, const void* src) {
    asm volatile("cp.async.cg.shared.global [%0], [%1], 16;\n" :: "r"(dst), "l"(src));
}
__device__ __forceinline__ void cp_commit() {
    asm volatile("cp.async.commit_group;\n");
}
template<int N>
__device__ __forceinline__ void cp_wait() {
    asm volatile("cp.async.wait_group %0;\n" :: "n"(N));
}

// issue one 64x64 16-bit tile (rows of 128B) into smem (byte stride 144), 128 threads
__device__ __forceinline__ void issue_tile(uint32_t sdst, const void* gsrc, int tid) {
    #pragma unroll
    for (int i = 0; i < 4; ++i) {
        int idx = i * 128 + tid;
        int r = idx >> 3, c = idx & 7;
        cp16(sdst + (uint32_t)(r * (ST * 2) + c * 16), (const char*)gsrc + r * 128 + c * 16);
    }
}

__global__ __launch_bounds__(128, 3)
void hd_attn_kernel(float* __restrict__ outp) {
    __shared__ __align__(16) char pool[4 * TILE_B];   // 36864 B
    __shared__ float srs[BM];
    __shared__ float svs[HD];

    const int tid = threadIdx.x;
    const int w = tid >> 5;
    const int lane = tid & 31;
    const int g = lane >> 2;
    const int qd = lane & 3;
    const int group = lane >> 3;
    const int lr = lane & 7;
    const int bh = blockIdx.y;
    const int m0 = blockIdx.x * BM;
    const size_t base = (size_t)bh * SEQ * HD;
    const float LSCALE = 0.0078125f;  // 1/128

    const int krow = (group >> 1) * 8 + lr;
    const int kcol = (group & 1) * 8;
    const int vrow = (group & 1) * 8 + lr;
    const int vcol = (group >> 1) * 8;

    const uint32_t pb = smem_u32(pool);
    const __nv_bfloat16* kg = g_kc + base;
    const half* vg = g_vc + base;

    // ---- stage Q and consume to regs ----
    {
        const char* qg = (const char*)(g_qc + base + (size_t)m0 * HD);
        #pragma unroll
        for (int i = 0; i < 8; ++i) {
            int idx = i * 128 + tid;
            int r = idx >> 3, c = idx & 7;
            cp16(pb + (uint32_t)(r * (ST * 2) + c * 16), qg + r * 128 + c * 16);
        }
        cp_commit();
    }
    if (tid < HD) svs[tid] = g_vsum[bh * HD + tid];
    cp_wait<0>();
    __syncthreads();

    const int r1 = w * 32 + g;
    uint32_t aq[4][8];
    {
        const __nv_bfloat16* sq = (const __nv_bfloat16*)pool;
        #pragma unroll
        for (int j = 0; j < 4; ++j) {
            int k0 = j * 16 + qd * 2;
            aq[j][0] = *(const uint32_t*)&sq[r1 * ST + k0];
            aq[j][1] = *(const uint32_t*)&sq[(r1 + 8) * ST + k0];
            aq[j][2] = *(const uint32_t*)&sq[r1 * ST + k0 + 8];
            aq[j][3] = *(const uint32_t*)&sq[(r1 + 8) * ST + k0 + 8];
            aq[j][4] = *(const uint32_t*)&sq[(r1 + 16) * ST + k0];
            aq[j][5] = *(const uint32_t*)&sq[(r1 + 24) * ST + k0];
            aq[j][6] = *(const uint32_t*)&sq[(r1 + 16) * ST + k0 + 8];
            aq[j][7] = *(const uint32_t*)&sq[(r1 + 24) * ST + k0 + 8];
        }
    }
    __syncthreads();

    // ---------------- pass 1: row sums, 4-deep K pipeline ----------------
    #pragma unroll
    for (int t = 0; t < 3; ++t) {
        issue_tile(pb + t * TILE_B, kg + (size_t)t * KT * HD, tid);
        cp_commit();
    }

    float rs[4] = {0.f, 0.f, 0.f, 0.f};
    for (int kb = 0; kb < SEQ / KT; ++kb) {
        if (kb + 3 < SEQ / KT)
            issue_tile(pb + ((kb + 3) & 3) * TILE_B, kg + (size_t)(kb + 3) * KT * HD, tid);
        cp_commit();
        cp_wait<3>();
        __syncthreads();

        const uint32_t sk_b = pb + (kb & 3) * TILE_B;
        #pragma unroll
        for (int tb = 0; tb < 4; ++tb) {
            float S2[2][2][4];
            #pragma unroll
            for (int blk = 0; blk < 2; ++blk)
                #pragma unroll
                for (int t = 0; t < 2; ++t)
                    { S2[blk][t][0]=0.f; S2[blk][t][1]=0.f; S2[blk][t][2]=0.f; S2[blk][t][3]=0.f; }
            #pragma unroll
            for (int j = 0; j < 4; ++j) {
                uint32_t b0, b1, b2, b3;
                ldsm_x4(b0, b1, b2, b3,
                        sk_b + 2u * (uint32_t)((tb * 16 + krow) * ST + j * 16 + kcol));
                mma_bf16(S2[0][0], &aq[j][0], b0, b1);
                mma_bf16(S2[0][1], &aq[j][0], b2, b3);
                mma_bf16(S2[1][0], &aq[j][4], b0, b1);
                mma_bf16(S2[1][1], &aq[j][4], b2, b3);
            }
            #pragma unroll
            for (int blk = 0; blk < 2; ++blk)
                #pragma unroll
                for (int t = 0; t < 2; ++t) {
                    rs[2*blk]   += __expf(S2[blk][t][0] * LSCALE) + __expf(S2[blk][t][1] * LSCALE);
                    rs[2*blk+1] += __expf(S2[blk][t][2] * LSCALE) + __expf(S2[blk][t][3] * LSCALE);
                }
        }
        __syncthreads();
    }
    #pragma unroll
    for (int i = 0; i < 4; ++i) {
        rs[i] += __shfl_xor_sync(0xffffffffu, rs[i], 1);
        rs[i] += __shfl_xor_sync(0xffffffffu, rs[i], 2);
    }
    if (qd == 0) {
        srs[r1] = rs[0]; srs[r1 + 8] = rs[1];
        srs[r1 + 16] = rs[2]; srs[r1 + 24] = rs[3];
    }
    __syncthreads();
    float inv[4];
    inv[0] = 1.f / srs[r1];      inv[1] = 1.f / srs[r1 + 8];
    inv[2] = 1.f / srs[r1 + 16]; inv[3] = 1.f / srs[r1 + 24];

    // ---------------- pass 2: 2-deep K+V pipeline ----------------
    float O[2][8][4];
    #pragma unroll
    for (int blk = 0; blk < 2; ++blk)
        #pragma unroll
        for (int nb = 0; nb < 8; ++nb)
            { O[blk][nb][0]=0.f; O[blk][nb][1]=0.f; O[blk][nb][2]=0.f; O[blk][nb][3]=0.f; }

    float* scr = outp + OUT_ELEMS + (size_t)bh * SEQ * SEQ + (size_t)(m0 + r1) * SEQ;

    issue_tile(pb,              kg, tid);
    issue_tile(pb + 2 * TILE_B, vg, tid);
    cp_commit();

    for (int kb = 0; kb < SEQ / KT; ++kb) {
        if (kb + 1 < SEQ / KT) {
            int nb1 = (kb + 1) & 1;
            issue_tile(pb + nb1 * TILE_B,       kg + (size_t)(kb + 1) * KT * HD, tid);
            issue_tile(pb + (2 + nb1) * TILE_B, vg + (size_t)(kb + 1) * KT * HD, tid);
        }
        cp_commit();
        cp_wait<1>();
        __syncthreads();

        const uint32_t sk_b  = pb + (kb & 1) * TILE_B;
        const uint32_t svh_b = pb + (2 + (kb & 1)) * TILE_B;

        #pragma unroll
        for (int tb = 0; tb < 4; ++tb) {
            // QK for this 16-token block
            float S2[2][2][4];
            #pragma unroll
            for (int blk = 0; blk < 2; ++blk)
                #pragma unroll
                for (int t = 0; t < 2; ++t)
                    { S2[blk][t][0]=0.f; S2[blk][t][1]=0.f; S2[blk][t][2]=0.f; S2[blk][t][3]=0.f; }
            #pragma unroll
            for (int j = 0; j < 4; ++j) {
                uint32_t b0, b1, b2, b3;
                ldsm_x4(b0, b1, b2, b3,
                        sk_b + 2u * (uint32_t)((tb * 16 + krow) * ST + j * 16 + kcol));
                mma_bf16(S2[0][0], &aq[j][0], b0, b1);
                mma_bf16(S2[0][1], &aq[j][0], b2, b3);
                mma_bf16(S2[1][0], &aq[j][4], b0, b1);
                mma_bf16(S2[1][1], &aq[j][4], b2, b3);
            }

            // exp, score store, pack e = p-1 as fp16 A-fragments
            uint32_t ea[2][4];
            #pragma unroll
            for (int blk = 0; blk < 2; ++blk) {
                #pragma unroll
                for (int t = 0; t < 2; ++t) {
                    float p0 = __expf(S2[blk][t][0] * LSCALE);
                    float p1 = __expf(S2[blk][t][1] * LSCALE);
                    float p2 = __expf(S2[blk][t][2] * LSCALE);
                    float p3 = __expf(S2[blk][t][3] * LSCALE);
                    int col = kb * KT + tb * 16 + t * 8 + qd * 2;
                    size_t ro = (size_t)(blk * 16) * SEQ;
                    __stcs((float2*)&scr[ro + col],
                           make_float2(p0 * inv[2*blk], p1 * inv[2*blk]));
                    __stcs((float2*)&scr[ro + (size_t)8 * SEQ + col],
                           make_float2(p2 * inv[2*blk+1], p3 * inv[2*blk+1]));
                    ea[blk][t*2]   = pack_h2(p0 - 1.f, p1 - 1.f);
                    ea[blk][t*2+1] = pack_h2(p2 - 1.f, p3 - 1.f);
                }
            }

            // EV k-step for this 16-token block
            #pragma unroll
            for (int d2 = 0; d2 < 4; ++d2) {
                uint32_t b0, b1, b2, b3;
                ldsm_x4_t(b0, b1, b2, b3,
                          svh_b + 2u * (uint32_t)((tb * 16 + vrow) * ST + d2 * 16 + vcol));
                mma_f16(O[0][2*d2],   ea[0], b0, b1);
                mma_f16(O[0][2*d2+1], ea[0], b2, b3);
                mma_f16(O[1][2*d2],   ea[1], b0, b1);
                mma_f16(O[1][2*d2+1], ea[1], b2, b3);
            }
        }
        __syncthreads();
    }

    // out = (vsum + O) / rowsum
    #pragma unroll
    for (int blk = 0; blk < 2; ++blk) {
        #pragma unroll
        for (int nb = 0; nb < 8; ++nb) {
            int d0 = nb * 8 + qd * 2;
            float vs0 = svs[d0], vs1 = svs[d0 + 1];
            float2 o0 = make_float2((O[blk][nb][0] + vs0) * inv[2*blk],
                                    (O[blk][nb][1] + vs1) * inv[2*blk]);
            float2 o1 = make_float2((O[blk][nb][2] + vs0) * inv[2*blk+1],
                                    (O[blk][nb][3] + vs1) * inv[2*blk+1]);
            int r = m0 + r1 + blk * 16;
            __stcs((float2*)&outp[base + (size_t)r * HD + d0], o0);
            __stcs((float2*)&outp[base + (size_t)(r + 8) * HD + d0], o1);
        }
    }
}

extern "C" void kernel_launch(void* const* d_in, const int* in_sizes, int n_in,
                              void* d_out, int out_size) {
    const float* q = (const float*)d_in[0];
    const float* k = (const float*)d_in[1];
    const float* v = (const float*)d_in[2];
    float* o = (float*)d_out;

    hd_convert_kernel<<<(int)(TOT / 4 / 512), 512>>>((const float4*)q, (const float4*)k,
                                                     (const float4*)v);
    hd_vsum_kernel<<<BHD, 1024>>>(v);
    dim3 grid(SEQ / BM, BHD);
    hd_attn_kernel<<<grid, 128>>>(o);
}